// round 8
// baseline (speedup 1.0000x reference)
#include <cuda_runtime.h>
#include <cuda_fp16.h>
#include <cstdint>

#define B_  256
#define T_  1024
#define H_  256

#define MT 32       // batch rows per group
#define NT 128      // permuted gate cols per CTA (32 hidden units x 4 gates)
#define NGROUP 8
#define NTILE  8
#define THREADS 256
#define CLUSTER 16  // 8 L0 CTAs (ranks 0-7) + 8 L1 CTAs (ranks 8-15)

#define WRS 264     // L1 y0-half weight row stride (halfs)
#define GS  132     // gate dump row stride (floats)
#define BLKB 2560   // bytes per producer block: 32 rows x 80B (ldsm conflict-free)
#define GBUF 20480  // 8 blocks = full 32x256 A tile

// ---- dynamic smem layout (bytes) ----
#define AS_Y     0                      // [2][GBUF] y0 tiles (L1)
#define AS_H     40960                  // [2][GBUF] h tiles
#define WS_OFF   81920                  // [NT][WRS] halfs (L1 y0 weights)
#define GS_OFF   149504                 // [MT][GS] floats
#define BIAS_OFF 166400
#define WX_OFF   166912
#define XS_OFF   167424                 // [2][MT] floats
#define MBAR_OFF 167680                 // mbarrier block (80B)
#define SMEM_TOTAL 167808

// mbar offsets within MBAR block (8B each, [buf] pairs)
#define MB_HARR  0    // h published (count 8)
#define MB_HTX   16   // h bulk tx (count 1)
#define MB_YARR  32   // y0 published (count 8)      [L1]
#define MB_YTX   48   // y0 bulk tx (count 1)        [L1]
#define MB_YFREE 64   // y0 slot consumed (count 8)  [L0]

// -------- persistent device scratch --------
// blocked layout: [t][grp][producer][row*40 + unit] halfs (80B rows)
__device__ __align__(16) __half g_y0[T_][NGROUP][NTILE][BLKB / 2];
__device__ __align__(16) __half g_h1[2][NGROUP][NTILE][BLKB / 2];

// -------- helpers --------
__device__ __forceinline__ uint32_t smem_u32(const void* p) {
    return (uint32_t)__cvta_generic_to_shared(p);
}
__device__ __forceinline__ float tanh_hw(float x) {
    float y;
    asm("tanh.approx.f32 %0, %1;" : "=f"(y) : "f"(x));
    return y;
}
__device__ __forceinline__ float sig_hw(float x) {
    return fmaf(0.5f, tanh_hw(0.5f * x), 0.5f);
}
__device__ __forceinline__ void mma16816(float* d, const uint32_t* a, uint32_t b0, uint32_t b1) {
    asm volatile(
        "mma.sync.aligned.m16n8k16.row.col.f32.f16.f16.f32 "
        "{%0,%1,%2,%3}, {%4,%5,%6,%7}, {%8,%9}, {%0,%1,%2,%3};\n"
        : "+f"(d[0]), "+f"(d[1]), "+f"(d[2]), "+f"(d[3])
        : "r"(a[0]), "r"(a[1]), "r"(a[2]), "r"(a[3]), "r"(b0), "r"(b1));
}
__device__ __forceinline__ void ldsm4(uint32_t* r, uint32_t addr) {
    asm volatile("ldmatrix.sync.aligned.m8n8.x4.shared.b16 {%0,%1,%2,%3}, [%4];"
        : "=r"(r[0]), "=r"(r[1]), "=r"(r[2]), "=r"(r[3]) : "r"(addr));
}
__device__ __forceinline__ void bulk_g2s(uint32_t dst, const void* src,
                                         uint32_t bytes, uint32_t mbar) {
    asm volatile(
        "cp.async.bulk.shared::cluster.global.mbarrier::complete_tx::bytes "
        "[%0], [%1], %2, [%3];"
        :: "r"(dst), "l"(src), "r"(bytes), "r"(mbar) : "memory");
}
__device__ __forceinline__ void mbar_init(uint32_t a, uint32_t cnt) {
    asm volatile("mbarrier.init.shared.b64 [%0], %1;" :: "r"(a), "r"(cnt) : "memory");
}
__device__ __forceinline__ void mbar_expect(uint32_t a, uint32_t bytes) {
    asm volatile("mbarrier.arrive.expect_tx.shared.b64 _, [%0], %1;"
                 :: "r"(a), "r"(bytes) : "memory");
}
// arrive on the same-offset mbar in cluster CTA `rank`
__device__ __forceinline__ void mbar_arrive_rank(uint32_t local_addr, uint32_t rank) {
    asm volatile(
        "{\n\t.reg .b32 ra;\n\t"
        "mapa.shared::cluster.u32 ra, %0, %1;\n\t"
        "mbarrier.arrive.shared::cluster.b64 _, [ra];\n\t}"
        :: "r"(local_addr), "r"(rank) : "memory");
}
__device__ __forceinline__ void mbar_wait_cta(uint32_t a, uint32_t par) {
    uint32_t done = 0;
    while (!done) {
        asm volatile(
            "{\n\t.reg .pred p;\n\t"
            "mbarrier.try_wait.parity.acquire.cta.shared::cta.b64 p, [%1], %2, 0x989680;\n\t"
            "selp.b32 %0, 1, 0, p;\n\t}"
            : "=r"(done) : "r"(a), "r"(par) : "memory");
    }
}
__device__ __forceinline__ void mbar_wait_clu(uint32_t a, uint32_t par) {
    uint32_t done = 0;
    while (!done) {
        asm volatile(
            "{\n\t.reg .pred p;\n\t"
            "mbarrier.try_wait.parity.acquire.cluster.shared::cta.b64 p, [%1], %2, 0x989680;\n\t"
            "selp.b32 %0, 1, 0, p;\n\t}"
            : "=r"(done) : "r"(a), "r"(par) : "memory");
    }
}
__device__ __forceinline__ void cluster_sync() {
    asm volatile("barrier.cluster.arrive.aligned;" ::: "memory");
    asm volatile("barrier.cluster.wait.aligned;" ::: "memory");
}

// ====================================================================
// Persistent LSTM layer. One 16-CTA cluster per batch group:
// ranks 0-7 = layer 0 tiles, ranks 8-15 = layer 1 tiles.
// Data goes through L2 (STG blocked slices, cp.async.bulk pulls);
// ALL signaling is DSMEM mbarrier arrives (no L2 flag polls):
//   hArr  : 8 peer CTAs published h (count 8)
//   hTx   : my 8 h bulk copies landed (tx)
//   yArr  : 8 L0 CTAs published y0[t]    (L1 only)
//   yTx   : my 8 y0 bulk copies landed   (L1 only)
//   yFree : 8 L1 CTAs consumed y0 slot   (L0 only; bounds skew so
//           mbar parity never aliases)
// ====================================================================
template <bool IS_L0>
__device__ __forceinline__ void run_layer(const float* __restrict__ x,
                                          const float* __restrict__ Wih,
                                          const float* __restrict__ Whh,
                                          const float* __restrict__ bih,
                                          const float* __restrict__ bhh,
                                          float* __restrict__ out,
                                          int layer_idx) {
    extern __shared__ char sm[];
    const uint32_t smb = smem_u32(sm);
    float*  Gs     = (float*)(sm + GS_OFF);
    float*  bias_s = (float*)(sm + BIAS_OFF);
    float*  wx_s   = (float*)(sm + WX_OFF);
    float*  xs     = (float*)(sm + XS_OFF);
    __half* Ws     = (__half*)(sm + WS_OFF);
    const uint32_t MB = smb + MBAR_OFF;

    const int tid  = threadIdx.x;
    const int lane = tid & 31, warp = tid >> 5;
    const int gid  = lane >> 2, tig = lane & 3;
    const int ntile = blockIdx.x & 7, grp = blockIdx.y;
    const int n0 = ntile * NT;
    const int b0 = grp * MT;
    const int j0 = n0 >> 2;

    // ---- mbar init, then cluster-wide visibility ----
    if (tid == 0) {
        mbar_init(MB + MB_HARR + 0, 8); mbar_init(MB + MB_HARR + 8, 8);
        mbar_init(MB + MB_HTX + 0, 1);  mbar_init(MB + MB_HTX + 8, 1);
        mbar_init(MB + MB_YARR + 0, 8); mbar_init(MB + MB_YARR + 8, 8);
        mbar_init(MB + MB_YTX + 0, 1);  mbar_init(MB + MB_YTX + 8, 1);
        mbar_init(MB + MB_YFREE + 0, 8); mbar_init(MB + MB_YFREE + 8, 8);
    }
    __syncthreads();
    cluster_sync();

    // ---- one-time: bias (+ scalar input weight for L0) ----
    if (tid < NT) {
        int n_g = n0 + tid;
        int p   = (n_g & 3) * H_ + (n_g >> 2);
        bias_s[tid] = bih[p] + bhh[p];
        if (IS_L0) wx_s[tid] = Wih[p];
    }

    // ---- one-time: h-half weights (Whh) into registers ----
    uint32_t bw[2][16][2];
    #pragma unroll
    for (int ni = 0; ni < 2; ni++) {
        int n_g = n0 + warp * 16 + ni * 8 + gid;
        int p   = (n_g & 3) * H_ + (n_g >> 2);
        const float* wr = Whh + (size_t)p * H_;
        #pragma unroll
        for (int kc = 0; kc < 16; kc++) {
            int k = kc * 16 + tig * 2;
            __half2 h01 = __floats2half2_rn(wr[k], wr[k + 1]);
            __half2 h89 = __floats2half2_rn(wr[k + 8], wr[k + 9]);
            bw[ni][kc][0] = *(uint32_t*)&h01;
            bw[ni][kc][1] = *(uint32_t*)&h89;
        }
    }

    // phase bitmasks (bit b = parity of buffer b)
    uint32_t phHA = 0, phHT = 0, phYA = 0, phYT = 0, phYF = 0;

    if constexpr (IS_L0) {
        if (tid < MT) xs[tid] = x[(size_t)(b0 + tid) * T_];
        __syncthreads();
    } else {
        // y0-half weights (Wih1, K=256) into smem
        for (int idx = tid; idx < NT * H_; idx += THREADS) {
            int nl = idx >> 8, k = idx & 255;
            int n_g = n0 + nl;
            int p   = (n_g & 3) * H_ + (n_g >> 2);
            Ws[nl * WRS + k] = __float2half_rn(Wih[(size_t)p * H_ + k]);
        }
        __syncthreads();
        // prologue: wait y0[0] published, pull it into A buf 0
        if (tid == 0) {
            mbar_wait_clu(MB + MB_YARR + 0, 0); phYA ^= 1u;
            mbar_expect(MB + MB_YTX + 0, GBUF);
            #pragma unroll
            for (int w = 0; w < 8; w++)
                bulk_g2s(smb + AS_Y + w * BLKB, &g_y0[0][grp][w][0],
                         BLKB, MB + MB_YTX + 0);
        }
    }

    // ---- per-lane ldsm byte offset within a blocked A tile ----
    const uint32_t aoffB = (uint32_t)((lane & 15) * 80 + ((lane >> 4) & 1) * 16);
    uint32_t bAddr = 0;
    if constexpr (!IS_L0) {
        int rB = warp * 16 + (lane & 7) + ((lane & 16) ? 8 : 0);
        int cB = (lane & 8) ? 8 : 0;
        bAddr = smb + WS_OFF + (uint32_t)((rB * WRS + cB) * 2);
    }

    const int m     = tid >> 3;
    const int ubase = (tid & 7) * 4;
    float creg[4] = {0.f, 0.f, 0.f, 0.f};

    for (int t = 0; t < T_; ++t) {
        const int cb = t & 1, nb = cb ^ 1;
        const uint32_t hbase = smb + AS_H + (uint32_t)cb * GBUF;

        // ---- h path: wait peer publishes, pull 8 blocks via L2 bulk ----
        if (t > 0 && tid == 0) {
            mbar_wait_clu(MB + MB_HARR + cb * 8, (phHA >> cb) & 1u);
            phHA ^= 1u << cb;
            mbar_expect(MB + MB_HTX + cb * 8, GBUF);
            #pragma unroll
            for (int w = 0; w < 8; w++) {
                const void* src = IS_L0 ? (const void*)&g_y0[t - 1][grp][w][0]
                                        : (const void*)&g_h1[cb][grp][w][0];
                bulk_g2s(hbase + w * BLKB, src, BLKB, MB + MB_HTX + cb * 8);
            }
        }

        float acc[2][2][4];
        #pragma unroll
        for (int mi = 0; mi < 2; mi++)
            #pragma unroll
            for (int ni = 0; ni < 2; ni++)
                #pragma unroll
                for (int r = 0; r < 4; r++) acc[mi][ni][r] = 0.f;

        // ---- L1: y0-half GEMM (independent of h; hides h bulk) ----
        if constexpr (!IS_L0) {
            mbar_wait_cta(MB + MB_YTX + cb * 8, (phYT >> cb) & 1u);
            phYT ^= 1u << cb;
            if (tid == 0) {      // release the y0 slot back to L0
                #pragma unroll
                for (int r = 0; r < 8; r++)
                    mbar_arrive_rank(MB + MB_YFREE + cb * 8, (uint32_t)r);
            }
            const uint32_t ybase = smb + AS_Y + (uint32_t)cb * GBUF;
            #pragma unroll
            for (int kc = 0; kc < 16; kc++) {
                uint32_t a0[4], a1[4], bb[4];
                const uint32_t ad = ybase + (kc >> 1) * BLKB + (kc & 1) * 32 + aoffB;
                ldsm4(a0, ad);
                ldsm4(a1, ad + 1280);
                ldsm4(bb, bAddr + kc * 32u);
                mma16816(acc[0][0], a0, bb[0], bb[1]);
                mma16816(acc[0][1], a0, bb[2], bb[3]);
                mma16816(acc[1][0], a1, bb[0], bb[1]);
                mma16816(acc[1][1], a1, bb[2], bb[3]);
            }
        }

        // ---- h-half GEMM (skipped at t=0: h == 0) ----
        if (t > 0) {
            mbar_wait_cta(MB + MB_HTX + cb * 8, (phHT >> cb) & 1u);
            phHT ^= 1u << cb;
            #pragma unroll
            for (int kc = 0; kc < 16; kc++) {
                uint32_t a0[4], a1[4];
                const uint32_t ad = hbase + (kc >> 1) * BLKB + (kc & 1) * 32 + aoffB;
                ldsm4(a0, ad);
                ldsm4(a1, ad + 1280);
                mma16816(acc[0][0], a0, bw[0][kc][0], bw[0][kc][1]);
                mma16816(acc[0][1], a0, bw[1][kc][0], bw[1][kc][1]);
                mma16816(acc[1][0], a1, bw[0][kc][0], bw[0][kc][1]);
                mma16816(acc[1][1], a1, bw[1][kc][0], bw[1][kc][1]);
            }
        }

        // ---- dump accumulators so each thread owns whole units ----
        #pragma unroll
        for (int mi = 0; mi < 2; mi++)
            #pragma unroll
            for (int ni = 0; ni < 2; ni++) {
                float* gp = Gs + (mi * 16 + gid) * GS + warp * 16 + ni * 8 + tig * 2;
                *(float2*)gp            = make_float2(acc[mi][ni][0], acc[mi][ni][1]);
                *(float2*)(gp + 8 * GS) = make_float2(acc[mi][ni][2], acc[mi][ni][3]);
            }
        __syncthreads();

        // ---- elementwise: 4 hidden units of one batch row ----
        float hv[4];
        float xv = IS_L0 ? xs[cb * MT + m] : 0.f;
        #pragma unroll
        for (int e = 0; e < 4; e++) {
            int nl = (ubase + e) * 4;
            const float4 gv = *(const float4*)(Gs + m * GS + nl);
            float pi = gv.x + bias_s[nl + 0];
            float pf = gv.y + bias_s[nl + 1];
            float pg = gv.z + bias_s[nl + 2];
            float po = gv.w + bias_s[nl + 3];
            if constexpr (IS_L0) {
                pi += xv * wx_s[nl + 0];
                pf += xv * wx_s[nl + 1];
                pg += xv * wx_s[nl + 2];
                po += xv * wx_s[nl + 3];
            }
            float ig = sig_hw(pi), fg = sig_hw(pf);
            float gg = tanh_hw(pg), og = sig_hw(po);
            float c  = fg * creg[e] + ig * gg;
            creg[e]  = c;
            hv[e]    = og * tanh_hw(c);
        }

        // ---- publish (blocked layout, 8B per thread) ----
        __half2 p01 = __floats2half2_rn(hv[0], hv[1]);
        __half2 p23 = __floats2half2_rn(hv[2], hv[3]);
        uint2 pk = make_uint2(*(uint32_t*)&p01, *(uint32_t*)&p23);
        if constexpr (IS_L0) {
            *(uint2*)&g_y0[t][grp][ntile][m * 40 + ubase] = pk;
        } else {
            if (t + 1 < T_)
                *(uint2*)&g_h1[nb][grp][ntile][m * 40 + ubase] = pk;
        }
        if (t == T_ - 1) {
            size_t oidx = ((size_t)layer_idx * B_ + (b0 + m)) * H_ + j0 + ubase;
            *(float4*)(out + oidx) = make_float4(hv[0], hv[1], hv[2], hv[3]);
            *(float4*)(out + (size_t)2 * B_ * H_ + oidx) =
                make_float4(creg[0], creg[1], creg[2], creg[3]);
        }

        __syncthreads();   // all publish STGs done

        // ---- signal consumers via DSMEM arrives (no L2 flags) ----
        if constexpr (IS_L0) {
            if (tid == 0) {
                __threadfence();   // STGs visible before arrives
                if (t >= 2) {      // backpressure: L1 must have consumed this slot
                    mbar_wait_clu(MB + MB_YFREE + cb * 8, (phYF >> cb) & 1u);
                    phYF ^= 1u << cb;
                }
                #pragma unroll
                for (int r = 0; r < 8; r++)
                    mbar_arrive_rank(MB + MB_HARR + nb * 8, (uint32_t)r);
                #pragma unroll
                for (int r = 0; r < 8; r++)
                    mbar_arrive_rank(MB + MB_YARR + cb * 8, (uint32_t)(8 + r));
            }
            if (tid < MT && t + 1 < T_)
                xs[nb * MT + tid] = x[(size_t)(b0 + tid) * T_ + (t + 1)];
        } else {
            if (tid == 0 && t + 1 < T_) {
                __threadfence();
                #pragma unroll
                for (int r = 0; r < 8; r++)
                    mbar_arrive_rank(MB + MB_HARR + nb * 8, (uint32_t)(8 + r));
                // tail: wait y0[t+1] published, pull it for next step
                mbar_wait_clu(MB + MB_YARR + nb * 8, (phYA >> nb) & 1u);
                phYA ^= 1u << nb;
                mbar_expect(MB + MB_YTX + nb * 8, GBUF);
                #pragma unroll
                for (int w = 0; w < 8; w++)
                    bulk_g2s(smb + AS_Y + (uint32_t)nb * GBUF + w * BLKB,
                             &g_y0[t + 1][grp][w][0], BLKB, MB + MB_YTX + nb * 8);
            }
        }
    }
    cluster_sync();   // no CTA exits while peer arrives are in flight
}

__global__ void __launch_bounds__(THREADS, 1)
lstm_fused_kernel(const float* __restrict__ x,
                  const float* __restrict__ Wih0, const float* __restrict__ Whh0,
                  const float* __restrict__ bih0, const float* __restrict__ bhh0,
                  const float* __restrict__ Wih1, const float* __restrict__ Whh1,
                  const float* __restrict__ bih1, const float* __restrict__ bhh1,
                  float* __restrict__ out) {
    if ((blockIdx.x >> 3) == 0)
        run_layer<true >(x, Wih0, Whh0, bih0, bhh0, out, 0);
    else
        run_layer<false>(nullptr, Wih1, Whh1, bih1, bhh1, out, 1);
}

extern "C" void kernel_launch(void* const* d_in, const int* in_sizes, int n_in,
                              void* d_out, int out_size) {
    (void)in_sizes; (void)n_in; (void)out_size;
    const float* x    = (const float*)d_in[0];
    const float* Wih0 = (const float*)d_in[1];
    const float* Whh0 = (const float*)d_in[2];
    const float* bih0 = (const float*)d_in[3];
    const float* bhh0 = (const float*)d_in[4];
    const float* Wih1 = (const float*)d_in[5];
    const float* Whh1 = (const float*)d_in[6];
    const float* bih1 = (const float*)d_in[7];
    const float* bhh1 = (const float*)d_in[8];
    float* out = (float*)d_out;

    cudaFuncSetAttribute((const void*)&lstm_fused_kernel,
                         cudaFuncAttributeMaxDynamicSharedMemorySize, SMEM_TOTAL);
    cudaFuncSetAttribute((const void*)&lstm_fused_kernel,
                         cudaFuncAttributeNonPortableClusterSizeAllowed, 1);

    cudaLaunchConfig_t cfg = {};
    cfg.gridDim  = dim3(2 * NTILE, NGROUP, 1);   // 16 x 8 = 128 CTAs
    cfg.blockDim = dim3(THREADS, 1, 1);
    cfg.dynamicSmemBytes = SMEM_TOTAL;
    cfg.stream = 0;
    cudaLaunchAttribute attrs[1];
    attrs[0].id = cudaLaunchAttributeClusterDimension;
    attrs[0].val.clusterDim = {CLUSTER, 1, 1};
    cfg.attrs = attrs;
    cfg.numAttrs = 1;

    cudaLaunchKernelEx(&cfg, lstm_fused_kernel,
                       x, Wih0, Whh0, bih0, bhh0, Wih1, Whh1, bih1, bhh1, out);
}

// round 9
// speedup vs baseline: 1.6658x; 1.6658x over previous
#include <cuda_runtime.h>
#include <cuda_fp16.h>
#include <cstdint>

#define B_  256
#define T_  1024
#define H_  256

#define MT 32       // batch rows per group
#define NT 128      // permuted gate cols per CTA (32 hidden units x 4 gates)
#define NGROUP 8
#define NTILE  8
#define THREADS 256

#define WRS 264     // L1 y0-half weight row stride (halfs)
#define GS  132     // gate dump row stride (floats)
#define BLKB 2560   // bytes per producer block: 32 rows x 80B (ldsm conflict-free)
#define GBUF 20480  // 8 blocks = full 32x256 A tile

// ---- dynamic smem layout (bytes) ----
#define AS_Y     0                      // [3][GBUF] y0 slots (L1)
#define AS_H     61440                  // [2][GBUF] h tiles
#define WS_OFF   102400                 // [NT][WRS] halfs (L1 y0 weights)
#define GS_OFF   169984                 // [MT][GS] floats
#define BIAS_OFF 186880
#define WX_OFF   187392
#define XS_OFF   187904                 // [2][MT] floats
#define MBAR_OFF 188160                 // mbarrier block
#define SMEM_TOTAL 188288

// mbar byte offsets within MBAR block (8B each)
#define MB_HTX   0    // h bulk tx: [buf][half] -> 0,8,16,24
#define MB_YTX   32   // y0 bulk tx: [slot] -> 32,40,48

// -------- persistent device scratch --------
// blocked layout: [t][grp][producer][row*40 + unit] halfs (80B rows)
__device__ __align__(16) __half g_y0[T_][NGROUP][NTILE][BLKB / 2];
__device__ __align__(16) __half g_h1[2][NGROUP][NTILE][BLKB / 2];
__device__ unsigned g_flag[2][NGROUP][NTILE][32];   // 128B-strided monotonic flags

__global__ void init_kernel() {
    int i = threadIdx.x;
    if (i < 2 * NGROUP * NTILE) ((unsigned*)g_flag)[i * 32] = 0u;
}

// -------- helpers --------
__device__ __forceinline__ uint32_t smem_u32(const void* p) {
    return (uint32_t)__cvta_generic_to_shared(p);
}
__device__ __forceinline__ unsigned ld_acq(const unsigned* p) {
    unsigned v;
    asm volatile("ld.acquire.gpu.global.u32 %0, [%1];" : "=r"(v) : "l"(p) : "memory");
    return v;
}
__device__ __forceinline__ void st_rel(unsigned* p, unsigned v) {
    asm volatile("st.release.gpu.global.u32 [%0], %1;" :: "l"(p), "r"(v) : "memory");
}
__device__ __forceinline__ float tanh_hw(float x) {
    float y;
    asm("tanh.approx.f32 %0, %1;" : "=f"(y) : "f"(x));
    return y;
}
__device__ __forceinline__ float sig_hw(float x) {
    return fmaf(0.5f, tanh_hw(0.5f * x), 0.5f);
}
__device__ __forceinline__ void mma16816(float* d, const uint32_t* a, uint32_t b0, uint32_t b1) {
    asm volatile(
        "mma.sync.aligned.m16n8k16.row.col.f32.f16.f16.f32 "
        "{%0,%1,%2,%3}, {%4,%5,%6,%7}, {%8,%9}, {%0,%1,%2,%3};\n"
        : "+f"(d[0]), "+f"(d[1]), "+f"(d[2]), "+f"(d[3])
        : "r"(a[0]), "r"(a[1]), "r"(a[2]), "r"(a[3]), "r"(b0), "r"(b1));
}
__device__ __forceinline__ void ldsm4(uint32_t* r, uint32_t addr) {
    asm volatile("ldmatrix.sync.aligned.m8n8.x4.shared.b16 {%0,%1,%2,%3}, [%4];"
        : "=r"(r[0]), "=r"(r[1]), "=r"(r[2]), "=r"(r[3]) : "r"(addr));
}
__device__ __forceinline__ void bulk_g2s(uint32_t dst, const void* src,
                                         uint32_t bytes, uint32_t mbar) {
    asm volatile(
        "cp.async.bulk.shared::cluster.global.mbarrier::complete_tx::bytes "
        "[%0], [%1], %2, [%3];"
        :: "r"(dst), "l"(src), "r"(bytes), "r"(mbar) : "memory");
}
__device__ __forceinline__ void mbar_init(uint32_t a, uint32_t cnt) {
    asm volatile("mbarrier.init.shared.b64 [%0], %1;" :: "r"(a), "r"(cnt) : "memory");
}
__device__ __forceinline__ void mbar_expect(uint32_t a, uint32_t bytes) {
    asm volatile("mbarrier.arrive.expect_tx.shared.b64 _, [%0], %1;"
                 :: "r"(a), "r"(bytes) : "memory");
}
__device__ __forceinline__ void mbar_wait(uint32_t a, uint32_t par) {
    uint32_t done = 0;
    while (!done) {
        asm volatile(
            "{\n\t.reg .pred p;\n\t"
            "mbarrier.try_wait.parity.acquire.cta.shared::cta.b64 p, [%1], %2, 0x989680;\n\t"
            "selp.b32 %0, 1, 0, p;\n\t}"
            : "=r"(done) : "r"(a), "r"(par) : "memory");
    }
}

// ====================================================================
// Persistent LSTM layer, 8 CTAs per batch group, L2 exchange via
// cp.async.bulk into ldsm-ready blocked smem (80B rows, conflict-free).
//  - producer publishes its 2.5KB blocked slice + st.release flag
//    (monotonic, value = t+1 after step t).
//  - consumer warp w: lane0 polls producer w's flag, issues ONE bulk;
//    two half-mbarriers let GEMM on blocks 0-3 overlap arrival of 4-7.
//  - L0's h buffer IS g_y0[t-1] (published once, consumed by both layers).
//  - L1: 3-slot y0 pipeline with prefetch distance 2 — at step t's tail
//    it fetches y0[t+2], so L0 jitter + flag discovery + bulk latency
//    are absorbed by a full step of slack (L0 free-runs ahead).
// ====================================================================
template <bool IS_L0>
__device__ __forceinline__ void run_layer(const float* __restrict__ x,
                                          const float* __restrict__ Wih,
                                          const float* __restrict__ Whh,
                                          const float* __restrict__ bih,
                                          const float* __restrict__ bhh,
                                          float* __restrict__ out,
                                          int layer_idx) {
    constexpr int L = IS_L0 ? 0 : 1;

    extern __shared__ char sm[];
    const uint32_t smb = smem_u32(sm);
    float*  Gs     = (float*)(sm + GS_OFF);
    float*  bias_s = (float*)(sm + BIAS_OFF);
    float*  wx_s   = (float*)(sm + WX_OFF);
    float*  xs     = (float*)(sm + XS_OFF);
    __half* Ws     = (__half*)(sm + WS_OFF);
    const uint32_t MB = smb + MBAR_OFF;

    const int tid  = threadIdx.x;
    const int lane = tid & 31, warp = tid >> 5;
    const int gid  = lane >> 2, tig = lane & 3;
    const int ntile = blockIdx.x, grp = blockIdx.y;
    const int n0 = ntile * NT;
    const int b0 = grp * MT;
    const int j0 = n0 >> 2;

    // ---- mbar init ----
    if (tid == 0) {
        mbar_init(MB + MB_HTX + 0, 1);  mbar_init(MB + MB_HTX + 8, 1);
        mbar_init(MB + MB_HTX + 16, 1); mbar_init(MB + MB_HTX + 24, 1);
        mbar_init(MB + MB_YTX + 0, 1);  mbar_init(MB + MB_YTX + 8, 1);
        mbar_init(MB + MB_YTX + 16, 1);
    }
    __syncthreads();

    // ---- one-time: bias (+ scalar input weight for L0) ----
    if (tid < NT) {
        int n_g = n0 + tid;
        int p   = (n_g & 3) * H_ + (n_g >> 2);
        bias_s[tid] = bih[p] + bhh[p];
        if (IS_L0) wx_s[tid] = Wih[p];
    }

    // ---- one-time: h-half weights (Whh) into registers ----
    uint32_t bw[2][16][2];
    #pragma unroll
    for (int ni = 0; ni < 2; ni++) {
        int n_g = n0 + warp * 16 + ni * 8 + gid;
        int p   = (n_g & 3) * H_ + (n_g >> 2);
        const float* wr = Whh + (size_t)p * H_;
        #pragma unroll
        for (int kc = 0; kc < 16; kc++) {
            int k = kc * 16 + tig * 2;
            __half2 h01 = __floats2half2_rn(wr[k], wr[k + 1]);
            __half2 h89 = __floats2half2_rn(wr[k + 8], wr[k + 9]);
            bw[ni][kc][0] = *(uint32_t*)&h01;
            bw[ni][kc][1] = *(uint32_t*)&h89;
        }
    }

    uint32_t phHT = 0;   // bit (buf*2+half): parity of h tx mbars
    uint32_t phY  = 0;   // bit slot: parity of y0 tx mbars

    if constexpr (IS_L0) {
        if (tid < MT) xs[tid] = x[(size_t)(b0 + tid) * T_];
        __syncthreads();
    } else {
        // y0-half weights (Wih1, K=256) into smem
        for (int idx = tid; idx < NT * H_; idx += THREADS) {
            int nl = idx >> 8, k = idx & 255;
            int n_g = n0 + nl;
            int p   = (n_g & 3) * H_ + (n_g >> 2);
            Ws[nl * WRS + k] = __float2half_rn(Wih[(size_t)p * H_ + k]);
        }
        // prologue: fetch y0[0] -> slot0 and y0[1] -> slot1
        if (tid == 0) {
            mbar_expect(MB + MB_YTX + 0, GBUF);
            mbar_expect(MB + MB_YTX + 8, GBUF);
        }
        __syncthreads();
        if (lane == 0) {
            while (ld_acq(&g_flag[0][grp][warp][0]) < 1u) { }
            bulk_g2s(smb + AS_Y + warp * BLKB, &g_y0[0][grp][warp][0],
                     BLKB, MB + MB_YTX + 0);
            while (ld_acq(&g_flag[0][grp][warp][0]) < 2u) { }
            bulk_g2s(smb + AS_Y + GBUF + warp * BLKB, &g_y0[1][grp][warp][0],
                     BLKB, MB + MB_YTX + 8);
        }
    }

    // ---- per-lane ldsm byte offset within a blocked A tile ----
    const uint32_t aoffB = (uint32_t)((lane & 15) * 80 + ((lane >> 4) & 1) * 16);
    uint32_t bAddr = 0;
    if constexpr (!IS_L0) {
        int rB = warp * 16 + (lane & 7) + ((lane & 16) ? 8 : 0);
        int cB = (lane & 8) ? 8 : 0;
        bAddr = smb + WS_OFF + (uint32_t)((rB * WRS + cB) * 2);
    }

    const int m     = tid >> 3;
    const int ubase = (tid & 7) * 4;
    float creg[4] = {0.f, 0.f, 0.f, 0.f};

    for (int t = 0; t < T_; ++t) {
        const int cb = t & 1, nb = cb ^ 1;
        const int ys = t % 3;                     // y0 slot for this step
        const uint32_t hbase = smb + AS_H + (uint32_t)cb * GBUF;

        // ---- issue h bulks first (copies fly during y0-GEMM) ----
        if (t > 0 && lane == 0) {
            while (ld_acq(&g_flag[L][grp][warp][0]) < (unsigned)t) { }
            const void* src = IS_L0 ? (const void*)&g_y0[t - 1][grp][warp][0]
                                    : (const void*)&g_h1[cb][grp][warp][0];
            bulk_g2s(hbase + warp * BLKB, src, BLKB,
                     MB + MB_HTX + cb * 16 + (warp >> 2) * 8);
        }

        float acc[2][2][4];
        #pragma unroll
        for (int mi = 0; mi < 2; mi++)
            #pragma unroll
            for (int ni = 0; ni < 2; ni++)
                #pragma unroll
                for (int r = 0; r < 4; r++) acc[mi][ni][r] = 0.f;

        // ---- L1: y0-half GEMM (independent of h; hides h bulk) ----
        if constexpr (!IS_L0) {
            mbar_wait(MB + MB_YTX + ys * 8, (phY >> ys) & 1u);
            phY ^= 1u << ys;
            const uint32_t ybase = smb + AS_Y + (uint32_t)ys * GBUF;
            #pragma unroll
            for (int kc = 0; kc < 16; kc++) {
                uint32_t a0[4], a1[4], bb[4];
                const uint32_t ad = ybase + (kc >> 1) * BLKB + (kc & 1) * 32 + aoffB;
                ldsm4(a0, ad);
                ldsm4(a1, ad + 1280);
                ldsm4(bb, bAddr + kc * 32u);
                mma16816(acc[0][0], a0, bb[0], bb[1]);
                mma16816(acc[0][1], a0, bb[2], bb[3]);
                mma16816(acc[1][0], a1, bb[0], bb[1]);
                mma16816(acc[1][1], a1, bb[2], bb[3]);
            }
        }

        // ---- h-half GEMM, two halves overlapped with arrival ----
        if (t > 0) {
            mbar_wait(MB + MB_HTX + cb * 16 + 0, (phHT >> (cb * 2)) & 1u);
            phHT ^= 1u << (cb * 2);
            #pragma unroll
            for (int kc = 0; kc < 8; kc++) {
                uint32_t a0[4], a1[4];
                const uint32_t ad = hbase + (kc >> 1) * BLKB + (kc & 1) * 32 + aoffB;
                ldsm4(a0, ad);
                ldsm4(a1, ad + 1280);
                mma16816(acc[0][0], a0, bw[0][kc][0], bw[0][kc][1]);
                mma16816(acc[0][1], a0, bw[1][kc][0], bw[1][kc][1]);
                mma16816(acc[1][0], a1, bw[0][kc][0], bw[0][kc][1]);
                mma16816(acc[1][1], a1, bw[1][kc][0], bw[1][kc][1]);
            }
            mbar_wait(MB + MB_HTX + cb * 16 + 8, (phHT >> (cb * 2 + 1)) & 1u);
            phHT ^= 1u << (cb * 2 + 1);
            #pragma unroll
            for (int kc = 8; kc < 16; kc++) {
                uint32_t a0[4], a1[4];
                const uint32_t ad = hbase + (kc >> 1) * BLKB + (kc & 1) * 32 + aoffB;
                ldsm4(a0, ad);
                ldsm4(a1, ad + 1280);
                mma16816(acc[0][0], a0, bw[0][kc][0], bw[0][kc][1]);
                mma16816(acc[0][1], a0, bw[1][kc][0], bw[1][kc][1]);
                mma16816(acc[1][0], a1, bw[0][kc][0], bw[0][kc][1]);
                mma16816(acc[1][1], a1, bw[1][kc][0], bw[1][kc][1]);
            }
        }

        // ---- dump accumulators so each thread owns whole units ----
        #pragma unroll
        for (int mi = 0; mi < 2; mi++)
            #pragma unroll
            for (int ni = 0; ni < 2; ni++) {
                float* gp = Gs + (mi * 16 + gid) * GS + warp * 16 + ni * 8 + tig * 2;
                *(float2*)gp            = make_float2(acc[mi][ni][0], acc[mi][ni][1]);
                *(float2*)(gp + 8 * GS) = make_float2(acc[mi][ni][2], acc[mi][ni][3]);
            }
        __syncthreads();

        // ---- elementwise: 4 hidden units of one batch row ----
        float hv[4];
        float xv = IS_L0 ? xs[cb * MT + m] : 0.f;
        #pragma unroll
        for (int e = 0; e < 4; e++) {
            int nl = (ubase + e) * 4;
            const float4 gv = *(const float4*)(Gs + m * GS + nl);
            float pi = gv.x + bias_s[nl + 0];
            float pf = gv.y + bias_s[nl + 1];
            float pg = gv.z + bias_s[nl + 2];
            float po = gv.w + bias_s[nl + 3];
            if constexpr (IS_L0) {
                pi += xv * wx_s[nl + 0];
                pf += xv * wx_s[nl + 1];
                pg += xv * wx_s[nl + 2];
                po += xv * wx_s[nl + 3];
            }
            float ig = sig_hw(pi), fg = sig_hw(pf);
            float gg = tanh_hw(pg), og = sig_hw(po);
            float c  = fg * creg[e] + ig * gg;
            creg[e]  = c;
            hv[e]    = og * tanh_hw(c);
        }

        // ---- publish (blocked layout, 8B per thread) ----
        __half2 p01 = __floats2half2_rn(hv[0], hv[1]);
        __half2 p23 = __floats2half2_rn(hv[2], hv[3]);
        uint2 pk = make_uint2(*(uint32_t*)&p01, *(uint32_t*)&p23);
        if constexpr (IS_L0) {
            *(uint2*)&g_y0[t][grp][ntile][m * 40 + ubase] = pk;
        } else {
            if (t + 1 < T_)
                *(uint2*)&g_h1[nb][grp][ntile][m * 40 + ubase] = pk;
        }
        if (t == T_ - 1) {
            size_t oidx = ((size_t)layer_idx * B_ + (b0 + m)) * H_ + j0 + ubase;
            *(float4*)(out + oidx) = make_float4(hv[0], hv[1], hv[2], hv[3]);
            *(float4*)(out + (size_t)2 * B_ * H_ + oidx) =
                make_float4(creg[0], creg[1], creg[2], creg[3]);
        }

        // ---- expects for next step's buffers (before those bulks fire) ----
        if (tid == 0) {
            if (t + 1 < T_) {
                mbar_expect(MB + MB_HTX + nb * 16 + 0, GBUF / 2);
                mbar_expect(MB + MB_HTX + nb * 16 + 8, GBUF / 2);
            }
            if (!IS_L0 && t + 2 < T_)
                mbar_expect(MB + MB_YTX + ((t + 2) % 3) * 8, GBUF);
        }
        __syncthreads();   // all publish STGs + expects done

        if (tid == 0) {
            if (IS_L0 || t + 1 < T_) {
                __threadfence();
                st_rel(&g_flag[L][grp][ntile][0], (unsigned)(t + 1));
            }
        }

        // ---- tail prefetch for next steps ----
        if constexpr (IS_L0) {
            if (tid < MT && t + 1 < T_)
                xs[nb * MT + tid] = x[(size_t)(b0 + tid) * T_ + (t + 1)];
        } else {
            // fetch y0[t+2] into slot (t+2)%3 — 2 steps of slack
            if (t + 2 < T_ && lane == 0) {
                while (ld_acq(&g_flag[0][grp][warp][0]) < (unsigned)(t + 3)) { }
                bulk_g2s(smb + AS_Y + (uint32_t)((t + 2) % 3) * GBUF + warp * BLKB,
                         &g_y0[t + 2][grp][warp][0], BLKB,
                         MB + MB_YTX + ((t + 2) % 3) * 8);
            }
        }
    }
}

__global__ void __launch_bounds__(THREADS, 1)
lstm_fused_kernel(const float* __restrict__ x,
                  const float* __restrict__ Wih0, const float* __restrict__ Whh0,
                  const float* __restrict__ bih0, const float* __restrict__ bhh0,
                  const float* __restrict__ Wih1, const float* __restrict__ Whh1,
                  const float* __restrict__ bih1, const float* __restrict__ bhh1,
                  float* __restrict__ out) {
    if (blockIdx.z == 0)
        run_layer<true >(x, Wih0, Whh0, bih0, bhh0, out, 0);
    else
        run_layer<false>(nullptr, Wih1, Whh1, bih1, bhh1, out, 1);
}

extern "C" void kernel_launch(void* const* d_in, const int* in_sizes, int n_in,
                              void* d_out, int out_size) {
    (void)in_sizes; (void)n_in; (void)out_size;
    const float* x    = (const float*)d_in[0];
    const float* Wih0 = (const float*)d_in[1];
    const float* Whh0 = (const float*)d_in[2];
    const float* bih0 = (const float*)d_in[3];
    const float* bhh0 = (const float*)d_in[4];
    const float* Wih1 = (const float*)d_in[5];
    const float* Whh1 = (const float*)d_in[6];
    const float* bih1 = (const float*)d_in[7];
    const float* bhh1 = (const float*)d_in[8];
    float* out = (float*)d_out;

    cudaFuncSetAttribute((const void*)&lstm_fused_kernel,
                         cudaFuncAttributeMaxDynamicSharedMemorySize, SMEM_TOTAL);

    init_kernel<<<1, 128>>>();

    dim3 grid(NTILE, NGROUP, 2);
    lstm_fused_kernel<<<grid, THREADS, SMEM_TOTAL>>>(
        x, Wih0, Whh0, bih0, bhh0, Wih1, Whh1, bih1, bhh1, out);
}

// round 10
// speedup vs baseline: 1.8498x; 1.1104x over previous
#include <cuda_runtime.h>
#include <cuda_fp16.h>
#include <cstdint>

#define B_  256
#define T_  1024
#define H_  256

#define MT 32       // batch rows per group
#define NT 128      // permuted gate cols per CTA (32 hidden units x 4 gates)
#define NGROUP 8
#define NTILE  8
#define THREADS 288 // 8 compute warps + 1 comm warp

#define WRS 264     // L1 y0-half weight row stride (halfs)
#define GS  132     // gate dump row stride (floats)
#define BLKB 2560   // bytes per producer block: 32 rows x 80B (ldsm conflict-free)
#define GBUF 20480  // 8 blocks = full 32x256 A tile

// ---- dynamic smem layout (bytes) ----
#define AS_Y     0                      // [3][GBUF] y0 slots (L1)
#define AS_H     61440                  // [2][GBUF] h tiles
#define WS_OFF   102400                 // [NT][WRS] halfs (L1 y0 weights)
#define GS_OFF   169984                 // [MT][GS] floats
#define BIAS_OFF 186880
#define WX_OFF   187392
#define XS_OFF   187904                 // [2][MT] floats
#define MBAR_OFF 188160                 // mbarrier block
#define SMEM_TOTAL 188288

// mbar byte offsets within MBAR block (8B each)
#define MB_HTX   0    // h bulk tx: [buf][half] -> 0,8,16,24
#define MB_YTX   32   // y0 bulk tx: [slot] -> 32,40,48

// -------- persistent device scratch --------
// blocked layout: [t][grp][producer][row*40 + unit] halfs (80B rows)
__device__ __align__(16) __half g_y0[T_][NGROUP][NTILE][BLKB / 2];
__device__ __align__(16) __half g_h1[2][NGROUP][NTILE][BLKB / 2];
__device__ unsigned g_flag[2][NGROUP][NTILE][32];   // 128B-strided monotonic flags

__global__ void init_kernel() {
    int i = threadIdx.x;
    if (i < 2 * NGROUP * NTILE) ((unsigned*)g_flag)[i * 32] = 0u;
}

// -------- helpers --------
__device__ __forceinline__ uint32_t smem_u32(const void* p) {
    return (uint32_t)__cvta_generic_to_shared(p);
}
__device__ __forceinline__ unsigned ld_acq(const unsigned* p) {
    unsigned v;
    asm volatile("ld.acquire.gpu.global.u32 %0, [%1];" : "=r"(v) : "l"(p) : "memory");
    return v;
}
__device__ __forceinline__ void st_rel(unsigned* p, unsigned v) {
    asm volatile("st.release.gpu.global.u32 [%0], %1;" :: "l"(p), "r"(v) : "memory");
}
__device__ __forceinline__ void barx(int id, int n) {
    asm volatile("bar.sync %0, %1;" :: "r"(id), "r"(n) : "memory");
}
__device__ __forceinline__ float tanh_hw(float x) {
    float y;
    asm("tanh.approx.f32 %0, %1;" : "=f"(y) : "f"(x));
    return y;
}
__device__ __forceinline__ float sig_hw(float x) {
    return fmaf(0.5f, tanh_hw(0.5f * x), 0.5f);
}
__device__ __forceinline__ void mma16816(float* d, const uint32_t* a, uint32_t b0, uint32_t b1) {
    asm volatile(
        "mma.sync.aligned.m16n8k16.row.col.f32.f16.f16.f32 "
        "{%0,%1,%2,%3}, {%4,%5,%6,%7}, {%8,%9}, {%0,%1,%2,%3};\n"
        : "+f"(d[0]), "+f"(d[1]), "+f"(d[2]), "+f"(d[3])
        : "r"(a[0]), "r"(a[1]), "r"(a[2]), "r"(a[3]), "r"(b0), "r"(b1));
}
__device__ __forceinline__ void ldsm4(uint32_t* r, uint32_t addr) {
    asm volatile("ldmatrix.sync.aligned.m8n8.x4.shared.b16 {%0,%1,%2,%3}, [%4];"
        : "=r"(r[0]), "=r"(r[1]), "=r"(r[2]), "=r"(r[3]) : "r"(addr));
}
__device__ __forceinline__ void bulk_g2s(uint32_t dst, const void* src,
                                         uint32_t bytes, uint32_t mbar) {
    asm volatile(
        "cp.async.bulk.shared::cluster.global.mbarrier::complete_tx::bytes "
        "[%0], [%1], %2, [%3];"
        :: "r"(dst), "l"(src), "r"(bytes), "r"(mbar) : "memory");
}
__device__ __forceinline__ void mbar_init(uint32_t a, uint32_t cnt) {
    asm volatile("mbarrier.init.shared.b64 [%0], %1;" :: "r"(a), "r"(cnt) : "memory");
}
__device__ __forceinline__ void mbar_expect(uint32_t a, uint32_t bytes) {
    asm volatile("mbarrier.arrive.expect_tx.shared.b64 _, [%0], %1;"
                 :: "r"(a), "r"(bytes) : "memory");
}
__device__ __forceinline__ void mbar_wait(uint32_t a, uint32_t par) {
    uint32_t done = 0;
    while (!done) {
        asm volatile(
            "{\n\t.reg .pred p;\n\t"
            "mbarrier.try_wait.parity.acquire.cta.shared::cta.b64 p, [%1], %2, 0x989680;\n\t"
            "selp.b32 %0, 1, 0, p;\n\t}"
            : "=r"(done) : "r"(a), "r"(par) : "memory");
    }
}

// ====================================================================
// Persistent LSTM layer, 8 CTAs per batch group, warp-specialized:
//   warps 0-7 : compute (MMA + epilogue + publish). Never touch flags.
//   warp 8    : comm. After each step's publish barrier it does
//               fence + flag release, arms next-step mbar expects, then
//               lane w polls producer w's flag and issues that bulk the
//               moment it is ready (arrival-ordered, parallel lanes).
//               L1 lanes 8-15 run the y0 distance-2 prefetch the same way.
// Data through L2 (STG blocked slices -> cp.async.bulk), signaling via
// per-producer monotonic flags (release/acquire) + local tx mbarriers.
// ====================================================================
template <bool IS_L0>
__device__ __forceinline__ void run_layer(const float* __restrict__ x,
                                          const float* __restrict__ Wih,
                                          const float* __restrict__ Whh,
                                          const float* __restrict__ bih,
                                          const float* __restrict__ bhh,
                                          float* __restrict__ out,
                                          int layer_idx) {
    constexpr int L = IS_L0 ? 0 : 1;

    extern __shared__ char sm[];
    const uint32_t smb = smem_u32(sm);
    float*  Gs     = (float*)(sm + GS_OFF);
    float*  bias_s = (float*)(sm + BIAS_OFF);
    float*  wx_s   = (float*)(sm + WX_OFF);
    float*  xs     = (float*)(sm + XS_OFF);
    __half* Ws     = (__half*)(sm + WS_OFF);
    const uint32_t MB = smb + MBAR_OFF;

    const int tid  = threadIdx.x;
    const int lane = tid & 31, warp = tid >> 5;
    const int gid  = lane >> 2, tig = lane & 3;
    const int ntile = blockIdx.x, grp = blockIdx.y;
    const int n0 = ntile * NT;
    const int b0 = grp * MT;
    const int j0 = n0 >> 2;

    // ---- mbar init ----
    if (tid == 0) {
        mbar_init(MB + MB_HTX + 0, 1);  mbar_init(MB + MB_HTX + 8, 1);
        mbar_init(MB + MB_HTX + 16, 1); mbar_init(MB + MB_HTX + 24, 1);
        mbar_init(MB + MB_YTX + 0, 1);  mbar_init(MB + MB_YTX + 8, 1);
        mbar_init(MB + MB_YTX + 16, 1);
    }
    __syncthreads();

    // ---- one-time: bias (+ scalar input weight for L0) ----
    if (tid < NT) {
        int n_g = n0 + tid;
        int p   = (n_g & 3) * H_ + (n_g >> 2);
        bias_s[tid] = bih[p] + bhh[p];
        if (IS_L0) wx_s[tid] = Wih[p];
    }

    // ---- one-time: h-half weights (Whh) into registers (compute warps) ----
    uint32_t bw[2][16][2];
    if (warp < 8) {
        #pragma unroll
        for (int ni = 0; ni < 2; ni++) {
            int n_g = n0 + warp * 16 + ni * 8 + gid;
            int p   = (n_g & 3) * H_ + (n_g >> 2);
            const float* wr = Whh + (size_t)p * H_;
            #pragma unroll
            for (int kc = 0; kc < 16; kc++) {
                int k = kc * 16 + tig * 2;
                __half2 h01 = __floats2half2_rn(wr[k], wr[k + 1]);
                __half2 h89 = __floats2half2_rn(wr[k + 8], wr[k + 9]);
                bw[ni][kc][0] = *(uint32_t*)&h01;
                bw[ni][kc][1] = *(uint32_t*)&h89;
            }
        }
    }

    if constexpr (IS_L0) {
        if (tid < MT) xs[tid] = x[(size_t)(b0 + tid) * T_];
        __syncthreads();
    } else {
        // y0-half weights (Wih1, K=256) into smem
        for (int idx = tid; idx < NT * H_; idx += THREADS) {
            int nl = idx >> 8, k = idx & 255;
            int n_g = n0 + nl;
            int p   = (n_g & 3) * H_ + (n_g >> 2);
            Ws[nl * WRS + k] = __float2half_rn(Wih[(size_t)p * H_ + k]);
        }
        // prologue: arm slot0/slot1, comm warp fetches y0[0], y0[1]
        if (tid == 0) {
            mbar_expect(MB + MB_YTX + 0, GBUF);
            mbar_expect(MB + MB_YTX + 8, GBUF);
        }
        __syncthreads();
        if (warp == 8 && lane < 8) {
            while (ld_acq(&g_flag[0][grp][lane][0]) < 1u) { }
            bulk_g2s(smb + AS_Y + lane * BLKB, &g_y0[0][grp][lane][0],
                     BLKB, MB + MB_YTX + 0);
            while (ld_acq(&g_flag[0][grp][lane][0]) < 2u) { }
            bulk_g2s(smb + AS_Y + GBUF + lane * BLKB, &g_y0[1][grp][lane][0],
                     BLKB, MB + MB_YTX + 8);
        }
    }

    // ---- per-lane ldsm byte offset within a blocked A tile ----
    const uint32_t aoffB = (uint32_t)((lane & 15) * 80 + ((lane >> 4) & 1) * 16);
    uint32_t bAddr = 0;
    if constexpr (!IS_L0) {
        int rB = (warp & 7) * 16 + (lane & 7) + ((lane & 16) ? 8 : 0);
        int cB = (lane & 8) ? 8 : 0;
        bAddr = smb + WS_OFF + (uint32_t)((rB * WRS + cB) * 2);
    }

    if (warp < 8) {
        // ================= COMPUTE WARPS =================
        const int m     = tid >> 3;
        const int ubase = (tid & 7) * 4;
        float creg[4] = {0.f, 0.f, 0.f, 0.f};
        uint32_t phHT = 0, phY = 0;

        for (int t = 0; t < T_; ++t) {
            const int cb = t & 1, nb = cb ^ 1;
            const int ys = t % 3;
            const uint32_t hbase = smb + AS_H + (uint32_t)cb * GBUF;

            float acc[2][2][4];
            #pragma unroll
            for (int mi = 0; mi < 2; mi++)
                #pragma unroll
                for (int ni = 0; ni < 2; ni++)
                    #pragma unroll
                    for (int r = 0; r < 4; r++) acc[mi][ni][r] = 0.f;

            // ---- L1: y0-half GEMM (independent of h) ----
            if constexpr (!IS_L0) {
                mbar_wait(MB + MB_YTX + ys * 8, (phY >> ys) & 1u);
                phY ^= 1u << ys;
                const uint32_t ybase = smb + AS_Y + (uint32_t)ys * GBUF;
                #pragma unroll
                for (int kc = 0; kc < 16; kc++) {
                    uint32_t a0[4], a1[4], bb[4];
                    const uint32_t ad = ybase + (kc >> 1) * BLKB + (kc & 1) * 32 + aoffB;
                    ldsm4(a0, ad);
                    ldsm4(a1, ad + 1280);
                    ldsm4(bb, bAddr + kc * 32u);
                    mma16816(acc[0][0], a0, bb[0], bb[1]);
                    mma16816(acc[0][1], a0, bb[2], bb[3]);
                    mma16816(acc[1][0], a1, bb[0], bb[1]);
                    mma16816(acc[1][1], a1, bb[2], bb[3]);
                }
            }

            // ---- h-half GEMM, two halves overlapped with arrival ----
            if (t > 0) {
                mbar_wait(MB + MB_HTX + cb * 16 + 0, (phHT >> (cb * 2)) & 1u);
                phHT ^= 1u << (cb * 2);
                #pragma unroll
                for (int kc = 0; kc < 8; kc++) {
                    uint32_t a0[4], a1[4];
                    const uint32_t ad = hbase + (kc >> 1) * BLKB + (kc & 1) * 32 + aoffB;
                    ldsm4(a0, ad);
                    ldsm4(a1, ad + 1280);
                    mma16816(acc[0][0], a0, bw[0][kc][0], bw[0][kc][1]);
                    mma16816(acc[0][1], a0, bw[1][kc][0], bw[1][kc][1]);
                    mma16816(acc[1][0], a1, bw[0][kc][0], bw[0][kc][1]);
                    mma16816(acc[1][1], a1, bw[1][kc][0], bw[1][kc][1]);
                }
                mbar_wait(MB + MB_HTX + cb * 16 + 8, (phHT >> (cb * 2 + 1)) & 1u);
                phHT ^= 1u << (cb * 2 + 1);
                #pragma unroll
                for (int kc = 8; kc < 16; kc++) {
                    uint32_t a0[4], a1[4];
                    const uint32_t ad = hbase + (kc >> 1) * BLKB + (kc & 1) * 32 + aoffB;
                    ldsm4(a0, ad);
                    ldsm4(a1, ad + 1280);
                    mma16816(acc[0][0], a0, bw[0][kc][0], bw[0][kc][1]);
                    mma16816(acc[0][1], a0, bw[1][kc][0], bw[1][kc][1]);
                    mma16816(acc[1][0], a1, bw[0][kc][0], bw[0][kc][1]);
                    mma16816(acc[1][1], a1, bw[1][kc][0], bw[1][kc][1]);
                }
            }

            // ---- dump accumulators so each thread owns whole units ----
            #pragma unroll
            for (int mi = 0; mi < 2; mi++)
                #pragma unroll
                for (int ni = 0; ni < 2; ni++) {
                    float* gp = Gs + (mi * 16 + gid) * GS + warp * 16 + ni * 8 + tig * 2;
                    *(float2*)gp            = make_float2(acc[mi][ni][0], acc[mi][ni][1]);
                    *(float2*)(gp + 8 * GS) = make_float2(acc[mi][ni][2], acc[mi][ni][3]);
                }
            barx(1, 256);

            // ---- elementwise: 4 hidden units of one batch row ----
            float hv[4];
            float xv = IS_L0 ? xs[cb * MT + m] : 0.f;
            #pragma unroll
            for (int e = 0; e < 4; e++) {
                int nl = (ubase + e) * 4;
                const float4 gv = *(const float4*)(Gs + m * GS + nl);
                float pi = gv.x + bias_s[nl + 0];
                float pf = gv.y + bias_s[nl + 1];
                float pg = gv.z + bias_s[nl + 2];
                float po = gv.w + bias_s[nl + 3];
                if constexpr (IS_L0) {
                    pi += xv * wx_s[nl + 0];
                    pf += xv * wx_s[nl + 1];
                    pg += xv * wx_s[nl + 2];
                    po += xv * wx_s[nl + 3];
                }
                float ig = sig_hw(pi), fg = sig_hw(pf);
                float gg = tanh_hw(pg), og = sig_hw(po);
                float c  = fg * creg[e] + ig * gg;
                creg[e]  = c;
                hv[e]    = og * tanh_hw(c);
            }

            // ---- publish (blocked layout, 8B per thread) ----
            __half2 p01 = __floats2half2_rn(hv[0], hv[1]);
            __half2 p23 = __floats2half2_rn(hv[2], hv[3]);
            uint2 pk = make_uint2(*(uint32_t*)&p01, *(uint32_t*)&p23);
            if constexpr (IS_L0) {
                *(uint2*)&g_y0[t][grp][ntile][m * 40 + ubase] = pk;
            } else {
                if (t + 1 < T_)
                    *(uint2*)&g_h1[nb][grp][ntile][m * 40 + ubase] = pk;
            }
            if (t == T_ - 1) {
                size_t oidx = ((size_t)layer_idx * B_ + (b0 + m)) * H_ + j0 + ubase;
                *(float4*)(out + oidx) = make_float4(hv[0], hv[1], hv[2], hv[3]);
                *(float4*)(out + (size_t)2 * B_ * H_ + oidx) =
                    make_float4(creg[0], creg[1], creg[2], creg[3]);
            }

            barx(0, 288);   // hand off to comm warp (STGs done)

            if constexpr (IS_L0) {
                if (tid < MT && t + 1 < T_)
                    xs[nb * MT + tid] = x[(size_t)(b0 + tid) * T_ + (t + 1)];
            }
        }
    } else {
        // ================= COMM WARP =================
        for (int t = 0; t < T_; ++t) {
            const int nb = (t + 1) & 1;

            barx(0, 288);   // wait for compute publish of step t

            if (lane == 0) {
                __threadfence();
                st_rel(&g_flag[L][grp][ntile][0], (unsigned)(t + 1));
                // arm next step's buffers (before this warp issues bulks)
                if (t + 1 < T_) {
                    mbar_expect(MB + MB_HTX + nb * 16 + 0, GBUF / 2);
                    mbar_expect(MB + MB_HTX + nb * 16 + 8, GBUF / 2);
                }
                if (!IS_L0 && t + 2 < T_)
                    mbar_expect(MB + MB_YTX + ((t + 2) % 3) * 8, GBUF);
            }
            __syncwarp();

            // h blocks for step t+1: lane w serves producer w, issues as ready
            if (lane < 8 && t + 1 < T_) {
                while (ld_acq(&g_flag[L][grp][lane][0]) < (unsigned)(t + 1)) { }
                const void* src = IS_L0 ? (const void*)&g_y0[t][grp][lane][0]
                                        : (const void*)&g_h1[nb][grp][lane][0];
                bulk_g2s(smb + AS_H + (uint32_t)nb * GBUF + lane * BLKB, src,
                         BLKB, MB + MB_HTX + nb * 16 + (lane >> 2) * 8);
            }
            // y0[t+2] prefetch (L1): lanes 8-15 serve producers 0-7
            if (!IS_L0 && lane >= 8 && lane < 16 && t + 2 < T_) {
                const int pw = lane - 8;
                while (ld_acq(&g_flag[0][grp][pw][0]) < (unsigned)(t + 3)) { }
                bulk_g2s(smb + AS_Y + (uint32_t)((t + 2) % 3) * GBUF + pw * BLKB,
                         &g_y0[t + 2][grp][pw][0], BLKB,
                         MB + MB_YTX + ((t + 2) % 3) * 8);
            }
        }
    }
}

__global__ void __launch_bounds__(THREADS, 1)
lstm_fused_kernel(const float* __restrict__ x,
                  const float* __restrict__ Wih0, const float* __restrict__ Whh0,
                  const float* __restrict__ bih0, const float* __restrict__ bhh0,
                  const float* __restrict__ Wih1, const float* __restrict__ Whh1,
                  const float* __restrict__ bih1, const float* __restrict__ bhh1,
                  float* __restrict__ out) {
    if (blockIdx.z == 0)
        run_layer<true >(x, Wih0, Whh0, bih0, bhh0, out, 0);
    else
        run_layer<false>(nullptr, Wih1, Whh1, bih1, bhh1, out, 1);
}

extern "C" void kernel_launch(void* const* d_in, const int* in_sizes, int n_in,
                              void* d_out, int out_size) {
    (void)in_sizes; (void)n_in; (void)out_size;
    const float* x    = (const float*)d_in[0];
    const float* Wih0 = (const float*)d_in[1];
    const float* Whh0 = (const float*)d_in[2];
    const float* bih0 = (const float*)d_in[3];
    const float* bhh0 = (const float*)d_in[4];
    const float* Wih1 = (const float*)d_in[5];
    const float* Whh1 = (const float*)d_in[6];
    const float* bih1 = (const float*)d_in[7];
    const float* bhh1 = (const float*)d_in[8];
    float* out = (float*)d_out;

    cudaFuncSetAttribute((const void*)&lstm_fused_kernel,
                         cudaFuncAttributeMaxDynamicSharedMemorySize, SMEM_TOTAL);

    init_kernel<<<1, 128>>>();

    dim3 grid(NTILE, NGROUP, 2);
    lstm_fused_kernel<<<grid, THREADS, SMEM_TOTAL>>>(
        x, Wih0, Whh0, bih0, bhh0, Wih1, Whh1, bih1, bhh1, out);
}

// round 12
// speedup vs baseline: 2.2795x; 1.2323x over previous
#include <cuda_runtime.h>
#include <cuda_fp16.h>
#include <cstdint>

#define B_  256
#define T_  1024
#define H_  256

#define MT 32       // batch rows per group
#define NT 128      // permuted gate cols per CTA (32 hidden units x 4 gates)
#define NGROUP 8
#define NTILE  8
#define THREADS 288 // 8 compute warps + 1 comm warp

#define WRS 264     // L1 y0-half weight row stride (halfs)
#define BLKB 2560   // bytes per producer block: 32 rows x 80B (ldsm conflict-free)
#define GBUF 20480  // 8 blocks = full 32x256 A tile

// ---- dynamic smem layout (bytes) ----
#define AS_Y     0                      // [3][GBUF] y0 slots (L1)
#define AS_H     61440                  // [2][GBUF] h tiles
#define WS_OFF   102400                 // [NT][WRS] halfs (L1 y0 weights)
#define BIAS_OFF 169984                 // [NT] floats
#define WX_OFF   170496                 // [NT] floats (L0)
#define MBAR_OFF 171008                 // mbarrier block
#define SMEM_TOTAL 171072

// mbar byte offsets within MBAR block (8B each)
#define MB_HTX   0    // h bulk tx: [buf][half] -> 0,8,16,24
#define MB_YTX   32   // y0 bulk tx: [slot] -> 32,40,48

// -------- persistent device scratch --------
// blocked layout: [t][grp][producer][row*40 + unit] halfs (80B rows)
__device__ __align__(16) __half g_y0[T_][NGROUP][NTILE][BLKB / 2];
__device__ __align__(16) __half g_h1[2][NGROUP][NTILE][BLKB / 2];
__device__ unsigned g_flag[2][NGROUP][NTILE][32];   // 128B-strided counting flags

__global__ void init_kernel() {
    int i = threadIdx.x;
    if (i < 2 * NGROUP * NTILE) ((unsigned*)g_flag)[i * 32] = 0u;
}

// -------- helpers --------
__device__ __forceinline__ uint32_t smem_u32(const void* p) {
    return (uint32_t)__cvta_generic_to_shared(p);
}
__device__ __forceinline__ unsigned ld_acq(const unsigned* p) {
    unsigned v;
    asm volatile("ld.acquire.gpu.global.u32 %0, [%1];" : "=r"(v) : "l"(p) : "memory");
    return v;
}
__device__ __forceinline__ void red_add_rel(unsigned* p) {
    asm volatile("red.release.gpu.global.add.u32 [%0], 1;" :: "l"(p) : "memory");
}
__device__ __forceinline__ float tanh_hw(float x) {
    float y;
    asm("tanh.approx.f32 %0, %1;" : "=f"(y) : "f"(x));
    return y;
}
__device__ __forceinline__ float sig_hw(float x) {
    return fmaf(0.5f, tanh_hw(0.5f * x), 0.5f);
}
__device__ __forceinline__ void mma16816(float* d, const uint32_t* a, uint32_t b0, uint32_t b1) {
    asm volatile(
        "mma.sync.aligned.m16n8k16.row.col.f32.f16.f16.f32 "
        "{%0,%1,%2,%3}, {%4,%5,%6,%7}, {%8,%9}, {%0,%1,%2,%3};\n"
        : "+f"(d[0]), "+f"(d[1]), "+f"(d[2]), "+f"(d[3])
        : "r"(a[0]), "r"(a[1]), "r"(a[2]), "r"(a[3]), "r"(b0), "r"(b1));
}
__device__ __forceinline__ void ldsm4(uint32_t* r, uint32_t addr) {
    asm volatile("ldmatrix.sync.aligned.m8n8.x4.shared.b16 {%0,%1,%2,%3}, [%4];"
        : "=r"(r[0]), "=r"(r[1]), "=r"(r[2]), "=r"(r[3]) : "r"(addr));
}
__device__ __forceinline__ void bulk_g2s(uint32_t dst, const void* src,
                                         uint32_t bytes, uint32_t mbar) {
    asm volatile(
        "cp.async.bulk.shared::cluster.global.mbarrier::complete_tx::bytes "
        "[%0], [%1], %2, [%3];"
        :: "r"(dst), "l"(src), "r"(bytes), "r"(mbar) : "memory");
}
__device__ __forceinline__ void mbar_init(uint32_t a, uint32_t cnt) {
    asm volatile("mbarrier.init.shared.b64 [%0], %1;" :: "r"(a), "r"(cnt) : "memory");
}
__device__ __forceinline__ void mbar_expect(uint32_t a, uint32_t bytes) {
    asm volatile("mbarrier.arrive.expect_tx.shared.b64 _, [%0], %1;"
                 :: "r"(a), "r"(bytes) : "memory");
}
__device__ __forceinline__ void mbar_wait(uint32_t a, uint32_t par) {
    uint32_t done = 0;
    while (!done) {
        asm volatile(
            "{\n\t.reg .pred p;\n\t"
            "mbarrier.try_wait.parity.acquire.cta.shared::cta.b64 p, [%1], %2, 0x989680;\n\t"
            "selp.b32 %0, 1, 0, p;\n\t}"
            : "=r"(done) : "r"(a), "r"(par) : "memory");
    }
}

// ====================================================================
// Persistent LSTM layer, 8 CTAs per batch group, warp-specialized.
//   warps 0-7 : compute. NO CTA barriers in the loop. Epilogue uses
//               shfl.bfly(1) to pair-exchange gate halves; each thread
//               computes 4 (row,unit) cells, publishes 4 halfs, then
//               issues ONE red.release.add on the CTA's counting flag.
//   warp 8    : comm. Lane w polls producer w's flag (>= 256*(t+1)),
//               issues that producer's bulk as soon as ready. Lane 0
//               arms all mbar expects first; __syncwarp() after the
//               expects and at end of each iteration keeps the warp
//               convergent so (a) no bulk ever precedes its expect,
//               (b) the L0-gated y-prefetch lanes cannot outrun the
//               self-gated h-poll lanes (no mbar double-flip).
// Buffer-reuse safety: a CTA's publish into a reused g_h1/g_y0 slot
// happens only after its own tx-mbar waits, whose bulks were gated on
// ALL producers' counting flags — so every peer's previous pull of
// that slot completed first.
// ====================================================================
template <bool IS_L0>
__device__ __forceinline__ void run_layer(const float* __restrict__ x,
                                          const float* __restrict__ Wih,
                                          const float* __restrict__ Whh,
                                          const float* __restrict__ bih,
                                          const float* __restrict__ bhh,
                                          float* __restrict__ out,
                                          int layer_idx) {
    constexpr int L = IS_L0 ? 0 : 1;

    extern __shared__ char sm[];
    const uint32_t smb = smem_u32(sm);
    float*  bias_s = (float*)(sm + BIAS_OFF);
    float*  wx_s   = (float*)(sm + WX_OFF);
    __half* Ws     = (__half*)(sm + WS_OFF);
    const uint32_t MB = smb + MBAR_OFF;

    const int tid  = threadIdx.x;
    const int lane = tid & 31, warp = tid >> 5;
    const int gid  = lane >> 2, tig = lane & 3;
    const int ntile = blockIdx.x, grp = blockIdx.y;
    const int n0 = ntile * NT;
    const int b0 = grp * MT;
    const int j0 = n0 >> 2;

    // ---- mbar init ----
    if (tid == 0) {
        mbar_init(MB + MB_HTX + 0, 1);  mbar_init(MB + MB_HTX + 8, 1);
        mbar_init(MB + MB_HTX + 16, 1); mbar_init(MB + MB_HTX + 24, 1);
        mbar_init(MB + MB_YTX + 0, 1);  mbar_init(MB + MB_YTX + 8, 1);
        mbar_init(MB + MB_YTX + 16, 1);
    }
    __syncthreads();

    // ---- one-time: bias (+ scalar input weight for L0) into smem ----
    if (tid < NT) {
        int n_g = n0 + tid;
        int p   = (n_g & 3) * H_ + (n_g >> 2);
        bias_s[tid] = bih[p] + bhh[p];
        if (IS_L0) wx_s[tid] = Wih[p];
    }

    // ---- one-time: h-half weights (Whh) into registers (compute warps) ----
    uint32_t bw[2][16][2];
    if (warp < 8) {
        #pragma unroll
        for (int ni = 0; ni < 2; ni++) {
            int n_g = n0 + warp * 16 + ni * 8 + gid;
            int p   = (n_g & 3) * H_ + (n_g >> 2);
            const float* wr = Whh + (size_t)p * H_;
            #pragma unroll
            for (int kc = 0; kc < 16; kc++) {
                int k = kc * 16 + tig * 2;
                __half2 h01 = __floats2half2_rn(wr[k], wr[k + 1]);
                __half2 h89 = __floats2half2_rn(wr[k + 8], wr[k + 9]);
                bw[ni][kc][0] = *(uint32_t*)&h01;
                bw[ni][kc][1] = *(uint32_t*)&h89;
            }
        }
    }

    if constexpr (!IS_L0) {
        // y0-half weights (Wih1, K=256) into smem
        for (int idx = tid; idx < NT * H_; idx += THREADS) {
            int nl = idx >> 8, k = idx & 255;
            int n_g = n0 + nl;
            int p   = (n_g & 3) * H_ + (n_g >> 2);
            Ws[nl * WRS + k] = __float2half_rn(Wih[(size_t)p * H_ + k]);
        }
        if (tid == 0) {
            mbar_expect(MB + MB_YTX + 0, GBUF);
            mbar_expect(MB + MB_YTX + 8, GBUF);
        }
    }
    __syncthreads();

    if constexpr (!IS_L0) {
        // prologue: comm warp fetches y0[0] -> slot0, y0[1] -> slot1
        // (expects armed by tid 0 before the __syncthreads above)
        if (warp == 8 && lane < 8) {
            while (ld_acq(&g_flag[0][grp][lane][0]) < (1u << 8)) { }
            bulk_g2s(smb + AS_Y + lane * BLKB, &g_y0[0][grp][lane][0],
                     BLKB, MB + MB_YTX + 0);
            while (ld_acq(&g_flag[0][grp][lane][0]) < (2u << 8)) { }
            bulk_g2s(smb + AS_Y + GBUF + lane * BLKB, &g_y0[1][grp][lane][0],
                     BLKB, MB + MB_YTX + 8);
        }
    }

    // ---- per-lane ldsm byte offset within a blocked A tile ----
    const uint32_t aoffB = (uint32_t)((lane & 15) * 80 + ((lane >> 4) & 1) * 16);
    uint32_t bAddr = 0;
    if constexpr (!IS_L0) {
        int rB = (warp & 7) * 16 + (lane & 7) + ((lane & 16) ? 8 : 0);
        int cB = (lane & 8) ? 8 : 0;
        bAddr = smb + WS_OFF + (uint32_t)((rB * WRS + cB) * 2);
    }

    if (warp < 8) {
        // ================= COMPUTE WARPS =================
        const int r0 = gid + ((tig & 1) << 3);        // row for mi=0 (mi adds 16)
        const int u0 = (warp << 2) + (tig >> 1);      // unit for ni=0 (ni adds 2)

        // bias / wx for this thread's 2 units -> registers
        float4 breg[2], wreg[2];
        #pragma unroll
        for (int ni = 0; ni < 2; ni++) {
            breg[ni] = *(const float4*)(bias_s + 4 * (u0 + 2 * ni));
            if (IS_L0) wreg[ni] = *(const float4*)(wx_s + 4 * (u0 + 2 * ni));
        }
        const float* xr[2];
        if constexpr (IS_L0) {
            xr[0] = x + (size_t)(b0 + r0) * T_;
            xr[1] = x + (size_t)(b0 + r0 + 16) * T_;
        }

        float creg[2][2] = {{0.f, 0.f}, {0.f, 0.f}};
        uint32_t phHT = 0, phY = 0;

        for (int t = 0; t < T_; ++t) {
            const int cb = t & 1, nb = cb ^ 1;
            const int ys = t % 3;
            const uint32_t hbase = smb + AS_H + (uint32_t)cb * GBUF;

            float xv[2];
            if constexpr (IS_L0) { xv[0] = xr[0][t]; xv[1] = xr[1][t]; }

            float acc[2][2][4];
            #pragma unroll
            for (int mi = 0; mi < 2; mi++)
                #pragma unroll
                for (int ni = 0; ni < 2; ni++)
                    #pragma unroll
                    for (int r = 0; r < 4; r++) acc[mi][ni][r] = 0.f;

            // ---- L1: y0-half GEMM (independent of h) ----
            if constexpr (!IS_L0) {
                mbar_wait(MB + MB_YTX + ys * 8, (phY >> ys) & 1u);
                phY ^= 1u << ys;
                const uint32_t ybase = smb + AS_Y + (uint32_t)ys * GBUF;
                #pragma unroll
                for (int kc = 0; kc < 16; kc++) {
                    uint32_t a0[4], a1[4], bb[4];
                    const uint32_t ad = ybase + (kc >> 1) * BLKB + (kc & 1) * 32 + aoffB;
                    ldsm4(a0, ad);
                    ldsm4(a1, ad + 1280);
                    ldsm4(bb, bAddr + kc * 32u);
                    mma16816(acc[0][0], a0, bb[0], bb[1]);
                    mma16816(acc[0][1], a0, bb[2], bb[3]);
                    mma16816(acc[1][0], a1, bb[0], bb[1]);
                    mma16816(acc[1][1], a1, bb[2], bb[3]);
                }
            }

            // ---- h-half GEMM, two halves overlapped with arrival ----
            if (t > 0) {
                mbar_wait(MB + MB_HTX + cb * 16 + 0, (phHT >> (cb * 2)) & 1u);
                phHT ^= 1u << (cb * 2);
                #pragma unroll
                for (int kc = 0; kc < 8; kc++) {
                    uint32_t a0[4], a1[4];
                    const uint32_t ad = hbase + (kc >> 1) * BLKB + (kc & 1) * 32 + aoffB;
                    ldsm4(a0, ad);
                    ldsm4(a1, ad + 1280);
                    mma16816(acc[0][0], a0, bw[0][kc][0], bw[0][kc][1]);
                    mma16816(acc[0][1], a0, bw[1][kc][0], bw[1][kc][1]);
                    mma16816(acc[1][0], a1, bw[0][kc][0], bw[0][kc][1]);
                    mma16816(acc[1][1], a1, bw[1][kc][0], bw[1][kc][1]);
                }
                mbar_wait(MB + MB_HTX + cb * 16 + 8, (phHT >> (cb * 2 + 1)) & 1u);
                phHT ^= 1u << (cb * 2 + 1);
                #pragma unroll
                for (int kc = 8; kc < 16; kc++) {
                    uint32_t a0[4], a1[4];
                    const uint32_t ad = hbase + (kc >> 1) * BLKB + (kc & 1) * 32 + aoffB;
                    ldsm4(a0, ad);
                    ldsm4(a1, ad + 1280);
                    mma16816(acc[0][0], a0, bw[0][kc][0], bw[0][kc][1]);
                    mma16816(acc[0][1], a0, bw[1][kc][0], bw[1][kc][1]);
                    mma16816(acc[1][0], a1, bw[0][kc][0], bw[0][kc][1]);
                    mma16816(acc[1][1], a1, bw[1][kc][0], bw[1][kc][1]);
                }
            }

            // ---- shfl epilogue: pair-exchange gates, no smem round-trip ----
            // tig even holds (i,f), tig odd holds (g,o) of unit u0+2ni.
            // After bfly(1): even computes row (gid), odd computes row (gid+8).
            #pragma unroll
            for (int mi = 0; mi < 2; mi++) {
                #pragma unroll
                for (int ni = 0; ni < 2; ni++) {
                    float sa = (tig & 1) ? acc[mi][ni][0] : acc[mi][ni][2];
                    float sb = (tig & 1) ? acc[mi][ni][1] : acc[mi][ni][3];
                    float ra = __shfl_xor_sync(0xffffffffu, sa, 1, 32);
                    float rb = __shfl_xor_sync(0xffffffffu, sb, 1, 32);
                    float pi, pf, pg, po;
                    if (tig & 1) { pi = ra;            pf = rb;
                                   pg = acc[mi][ni][2]; po = acc[mi][ni][3]; }
                    else         { pi = acc[mi][ni][0]; pf = acc[mi][ni][1];
                                   pg = ra;             po = rb; }
                    pi += breg[ni].x; pf += breg[ni].y;
                    pg += breg[ni].z; po += breg[ni].w;
                    if constexpr (IS_L0) {
                        pi += xv[mi] * wreg[ni].x;
                        pf += xv[mi] * wreg[ni].y;
                        pg += xv[mi] * wreg[ni].z;
                        po += xv[mi] * wreg[ni].w;
                    }
                    float ig = sig_hw(pi), fg = sig_hw(pf);
                    float gg = tanh_hw(pg), og = sig_hw(po);
                    float c  = fg * creg[mi][ni] + ig * gg;
                    creg[mi][ni] = c;
                    float h  = og * tanh_hw(c);

                    const int row = r0 + 16 * mi;
                    const int u   = u0 + 2 * ni;
                    __half hh = __float2half_rn(h);
                    if constexpr (IS_L0) {
                        g_y0[t][grp][ntile][row * 40 + u] = hh;
                    } else {
                        if (t + 1 < T_)
                            g_h1[nb][grp][ntile][row * 40 + u] = hh;
                    }
                    if (t == T_ - 1) {
                        size_t oidx = ((size_t)layer_idx * B_ + (b0 + row)) * H_ + j0 + u;
                        out[oidx] = h;
                        out[(size_t)2 * B_ * H_ + oidx] = c;
                    }
                }
            }

            // ---- release: one counting-flag increment per thread ----
            if (IS_L0 || t + 1 < T_)
                red_add_rel(&g_flag[L][grp][ntile][0]);
        }
    } else {
        // ================= COMM WARP =================
        for (int t = 0; t < T_ - 1; ++t) {
            const int nb = (t + 1) & 1;

            // arm expects for this iteration's bulks (lane 0), then make
            // the whole warp wait so NO lane's bulk can precede them.
            if (lane == 0) {
                mbar_expect(MB + MB_HTX + nb * 16 + 0, GBUF / 2);
                mbar_expect(MB + MB_HTX + nb * 16 + 8, GBUF / 2);
                if (!IS_L0 && t + 2 < T_)
                    mbar_expect(MB + MB_YTX + ((t + 2) % 3) * 8, GBUF);
            }
            __syncwarp();

            // h blocks for step t+1: lane w serves producer w (self-gated:
            // the poll set includes our own CTA's flag at lane == ntile)
            if (lane < 8) {
                while (ld_acq(&g_flag[L][grp][lane][0]) <
                       (unsigned)((t + 1) << 8)) { }
                const void* src = IS_L0 ? (const void*)&g_y0[t][grp][lane][0]
                                        : (const void*)&g_h1[nb][grp][lane][0];
                bulk_g2s(smb + AS_H + (uint32_t)nb * GBUF + lane * BLKB, src,
                         BLKB, MB + MB_HTX + nb * 16 + (lane >> 2) * 8);
            }
            // y0[t+2] prefetch (L1): lanes 8-15 serve producers 0-7
            if (!IS_L0 && lane >= 8 && lane < 16 && t + 2 < T_) {
                const int pw = lane - 8;
                while (ld_acq(&g_flag[0][grp][pw][0]) <
                       (unsigned)((t + 3) << 8)) { }
                bulk_g2s(smb + AS_Y + (uint32_t)((t + 2) % 3) * GBUF + pw * BLKB,
                         &g_y0[t + 2][grp][pw][0], BLKB,
                         MB + MB_YTX + ((t + 2) % 3) * 8);
            }

            // reconverge: the L0-gated y lanes must not outrun the
            // self-gated h lanes into the next iteration (slot reuse safety)
            __syncwarp();
        }
    }
}

__global__ void __launch_bounds__(THREADS, 1)
lstm_fused_kernel(const float* __restrict__ x,
                  const float* __restrict__ Wih0, const float* __restrict__ Whh0,
                  const float* __restrict__ bih0, const float* __restrict__ bhh0,
                  const float* __restrict__ Wih1, const float* __restrict__ Whh1,
                  const float* __restrict__ bih1, const float* __restrict__ bhh1,
                  float* __restrict__ out) {
    if (blockIdx.z == 0)
        run_layer<true >(x, Wih0, Whh0, bih0, bhh0, out, 0);
    else
        run_layer<false>(nullptr, Wih1, Whh1, bih1, bhh1, out, 1);
}

extern "C" void kernel_launch(void* const* d_in, const int* in_sizes, int n_in,
                              void* d_out, int out_size) {
    (void)in_sizes; (void)n_in; (void)out_size;
    const float* x    = (const float*)d_in[0];
    const float* Wih0 = (const float*)d_in[1];
    const float* Whh0 = (const float*)d_in[2];
    const float* bih0 = (const float*)d_in[3];
    const float* bhh0 = (const float*)d_in[4];
    const float* Wih1 = (const float*)d_in[5];
    const float* Whh1 = (const float*)d_in[6];
    const float* bih1 = (const float*)d_in[7];
    const float* bhh1 = (const float*)d_in[8];
    float* out = (float*)d_out;

    cudaFuncSetAttribute((const void*)&lstm_fused_kernel,
                         cudaFuncAttributeMaxDynamicSharedMemorySize, SMEM_TOTAL);

    init_kernel<<<1, 128>>>();

    dim3 grid(NTILE, NGROUP, 2);
    lstm_fused_kernel<<<grid, THREADS, SMEM_TOTAL>>>(
        x, Wih0, Whh0, bih0, bhh0, Wih1, Whh1, bih1, bhh1, out);
}